// round 16
// baseline (speedup 1.0000x reference)
#include <cuda_runtime.h>
#include <cuda_fp16.h>
#include <cstdint>

// Problem constants: N=100000, S=8, B=4, F=128, O=64, E=3.2M
#define MAXN 100000
#define MAXE 3300000
#define FDIM 128
#define ODIM 64
#define NBAS 4
#define NREL 8

// Scratch (__device__ globals; no runtime alloc allowed)
__device__ __half g_FWh[(size_t)NREL * MAXN * ODIM];  // [8, N, 64] fp16 (102.4 MB)
__device__ __half g_Bh[NBAS * ODIM * FDIM];           // [4][n=64][k=128] fp16
__device__ int    g_cnt[MAXN];
__device__ int    g_off[MAXN + 1];
__device__ int    g_pos[MAXN];
__device__ uint2  g_pairs[MAXE];                      // (col, val-bits), row-sorted

// ---------------------------------------------------------------------------
__device__ __forceinline__ void mma_f16(float* d, uint32_t a0, uint32_t a1, uint32_t a2,
                                        uint32_t a3, uint32_t b0, uint32_t b1) {
    asm volatile(
        "mma.sync.aligned.m16n8k16.row.col.f32.f16.f16.f32 "
        "{%0,%1,%2,%3}, {%4,%5,%6,%7}, {%8,%9}, {%0,%1,%2,%3};"
        : "+f"(d[0]), "+f"(d[1]), "+f"(d[2]), "+f"(d[3])
        : "r"(a0), "r"(a1), "r"(a2), "r"(a3), "r"(b0), "r"(b1));
}

// ---------------------------------------------------------------------------
// Kernel 0: B~[b][n][k] = fp16( Bases[b][k][n] )
// ---------------------------------------------------------------------------
__global__ void bcomb_kernel(const float* __restrict__ bases) {
    int idx = blockIdx.x * blockDim.x + threadIdx.x;
    if (idx >= NBAS * FDIM * ODIM) return;
    int b = idx >> 13;
    int r = idx & 8191;
    int n = r >> 7;
    int k = r & 127;
    g_Bh[idx] = __float2half_rn(__ldg(bases + b * FDIM * ODIM + k * ODIM + n));
}

// ---------------------------------------------------------------------------
// Kernel 1: basis GEMM + in-register combine (r15 version, best known)
// ---------------------------------------------------------------------------
#define XS_STRIDE 136
#define BS_STRIDE 136
#define BS_BYTES  (64 * BS_STRIDE * 2)
#define ST_STRIDE 40
#define SM_ST_OFF (4 * BS_BYTES)
#define SMEM_GEMM (SM_ST_OFF + 16 * 16 * ST_STRIDE * 2)

__global__ void __launch_bounds__(512, 1) gemm_fw_kernel(const float* __restrict__ X,
                                                         const float* __restrict__ comp,
                                                         int nN) {
    extern __shared__ char smb[];
    __half* Xs = (__half*)smb;
    const int tid = threadIdx.x;
    const int wid = tid >> 5;
    const int lane = tid & 31;
    const int g = lane >> 2;
    const int tg = lane & 3;
    const int node0 = blockIdx.x * 128;
    const int wrow = (wid & 7) * 16;
    const int wc = (wid >> 3) * 32;

    {
        const float4* X4 = (const float4*)X;
        #pragma unroll 2
        for (int i = tid; i < 4096; i += 512) {
            int row = i >> 5, q = i & 31;
            int gn = node0 + row;
            float4 v = (gn < nN) ? __ldcs(X4 + (size_t)gn * 32 + q) : make_float4(0.f, 0.f, 0.f, 0.f);
            __half2 h0 = __floats2half2_rn(v.x, v.y);
            __half2 h1 = __floats2half2_rn(v.z, v.w);
            uint2 packed = make_uint2(*(uint32_t*)&h0, *(uint32_t*)&h1);
            *(uint2*)(Xs + row * XS_STRIDE + q * 4) = packed;
        }
    }
    __syncthreads();

    uint32_t a[8][4];
    #pragma unroll
    for (int ks = 0; ks < 8; ks++) {
        const __half* ar = Xs + (wrow + g) * XS_STRIDE + ks * 16 + tg * 2;
        a[ks][0] = *(const uint32_t*)(ar);
        a[ks][1] = *(const uint32_t*)(ar + 8 * XS_STRIDE);
        a[ks][2] = *(const uint32_t*)(ar + 8);
        a[ks][3] = *(const uint32_t*)(ar + 8 * XS_STRIDE + 8);
    }
    __syncthreads();

    {
        const uint4* src = (const uint4*)g_Bh;
        #pragma unroll
        for (int i = tid; i < 4096; i += 512) {
            int b = i >> 10, j = i & 1023;
            int n = j >> 4, q = j & 15;
            *(uint4*)(smb + b * BS_BYTES + (n * BS_STRIDE + q * 8) * 2) = __ldg(src + i);
        }
    }
    __syncthreads();

    float d[NBAS][4][4];
    #pragma unroll
    for (int b = 0; b < NBAS; b++)
        #pragma unroll
        for (int ni = 0; ni < 4; ni++)
            #pragma unroll
            for (int j = 0; j < 4; j++) d[b][ni][j] = 0.f;

    #pragma unroll
    for (int b = 0; b < NBAS; b++) {
        const __half* Bs = (const __half*)(smb + b * BS_BYTES);
        #pragma unroll
        for (int ks = 0; ks < 8; ks++) {
            #pragma unroll
            for (int ni = 0; ni < 4; ni++) {
                const __half* br = Bs + (wc + ni * 8 + g) * BS_STRIDE + ks * 16 + tg * 2;
                uint32_t b0 = *(const uint32_t*)(br);
                uint32_t b1 = *(const uint32_t*)(br + 8);
                mma_f16(d[b][ni], a[ks][0], a[ks][1], a[ks][2], a[ks][3], b0, b1);
            }
        }
    }

    __half* Stw = (__half*)(smb + SM_ST_OFF) + wid * 16 * ST_STRIDE;
    for (int s = 0; s < NREL; s++) {
        float c0 = __ldg(comp + s * NBAS + 0);
        float c1 = __ldg(comp + s * NBAS + 1);
        float c2 = __ldg(comp + s * NBAS + 2);
        float c3 = __ldg(comp + s * NBAS + 3);

        __half* s0 = Stw + g * ST_STRIDE;
        __half* s1 = Stw + (8 + g) * ST_STRIDE;
        #pragma unroll
        for (int ni = 0; ni < 4; ni++) {
            float f0 = c0*d[0][ni][0] + c1*d[1][ni][0] + c2*d[2][ni][0] + c3*d[3][ni][0];
            float f1 = c0*d[0][ni][1] + c1*d[1][ni][1] + c2*d[2][ni][1] + c3*d[3][ni][1];
            float f2 = c0*d[0][ni][2] + c1*d[1][ni][2] + c2*d[2][ni][2] + c3*d[3][ni][2];
            float f3 = c0*d[0][ni][3] + c1*d[1][ni][3] + c2*d[2][ni][3] + c3*d[3][ni][3];
            int c = ni * 8 + tg * 2;
            *(__half2*)(s0 + c) = __floats2half2_rn(f0, f1);
            *(__half2*)(s1 + c) = __floats2half2_rn(f2, f3);
        }
        __syncwarp();

        __half* fwbase = g_FWh + (size_t)s * nN * ODIM;
        #pragma unroll
        for (int j = 0; j < 2; j++) {
            int idx = lane + j * 32;
            int r = idx >> 2, q = idx & 3;
            int gn = node0 + wrow + r;
            if (gn < nN) {
                uint4 v = *(const uint4*)(Stw + r * ST_STRIDE + q * 8);
                *(uint4*)(fwbase + (size_t)gn * ODIM + wc + q * 8) = v;
            }
        }
        __syncwarp();
    }
}

// ---------------------------------------------------------------------------
// CSR build (round-7/11 design, correctness proven)
// ---------------------------------------------------------------------------
__global__ void zero_cnt_kernel(int nN) {
    int i = blockIdx.x * blockDim.x + threadIdx.x;
    if (i < nN) g_cnt[i] = 0;
}

__global__ void hist_kernel(const int* __restrict__ rows, int E) {
    int e = blockIdx.x * blockDim.x + threadIdx.x;
    if (e < E) atomicAdd(&g_cnt[__ldg(rows + e)], 1);
}

__global__ void __launch_bounds__(1024) scan_kernel(int nN) {
    __shared__ int ssum[1024];
    const int tid = threadIdx.x;
    const int chunk = (nN + 1023) / 1024;
    const int start = tid * chunk;
    const int end = min(start + chunk, nN);

    int sum = 0;
    for (int i = start; i < end; i++) sum += g_cnt[i];
    ssum[tid] = sum;
    __syncthreads();

    #pragma unroll
    for (int d = 1; d < 1024; d <<= 1) {
        int v = (tid >= d) ? ssum[tid - d] : 0;
        __syncthreads();
        ssum[tid] += v;
        __syncthreads();
    }
    int base = (tid == 0) ? 0 : ssum[tid - 1];

    for (int i = start; i < end; i++) {
        int c = g_cnt[i];
        g_off[i] = base;
        g_pos[i] = base;
        base += c;
    }
    if (tid == 1023) g_off[nN] = base;
}

__global__ void scatter_kernel(const int* __restrict__ rows, const int* __restrict__ cols,
                               const float* __restrict__ vals, int E) {
    int e = blockIdx.x * blockDim.x + threadIdx.x;
    if (e >= E) return;
    int r = __ldg(rows + e);
    int p = atomicAdd(&g_pos[r], 1);
    g_pairs[p] = make_uint2((uint32_t)__ldg(cols + e), __float_as_uint(__ldg(vals + e)));
}

// ---------------------------------------------------------------------------
// Kernel 2: wide-lane pull + fused bias/ReLU. Warp per row.
// 32 lanes = 4 edge-slots x 8 chunk-lanes. Per edge: ONE LDG.128 per lane
// (8 gather lane-ops/edge, the 16B-granularity floor), fp32 reg accumulate,
// 2 shfl-xor rounds per accumulator at row end. Zero atomics, zero REDG.
// ---------------------------------------------------------------------------
__global__ void __launch_bounds__(256) pull8_kernel(float* __restrict__ out,
                                                    const float* __restrict__ bias, int nN) {
    int row = blockIdx.x * 8 + (threadIdx.x >> 5);
    if (row >= nN) return;
    const int lane = threadIdx.x & 31;
    const int g = lane >> 3;      // edge slot 0..3
    const int l = lane & 7;       // chunk lane 0..7
    const uint32_t FULL = 0xFFFFFFFFu;

    const int beg = g_off[row];
    const int end = g_off[row + 1];

    float acc[8];
    #pragma unroll
    for (int j = 0; j < 8; j++) acc[j] = 0.f;

    for (int i = beg + g; i < end; i += 4) {
        uint2 p = __ldg(&g_pairs[i]);                 // 8 lanes/slot broadcast
        float v = __uint_as_float(p.y);
        uint4 h = *(const uint4*)(g_FWh + (size_t)p.x * ODIM + l * 8);
        float2 f0 = __half22float2(*(__half2*)&h.x);
        float2 f1 = __half22float2(*(__half2*)&h.y);
        float2 f2 = __half22float2(*(__half2*)&h.z);
        float2 f3 = __half22float2(*(__half2*)&h.w);
        acc[0] = fmaf(v, f0.x, acc[0]); acc[1] = fmaf(v, f0.y, acc[1]);
        acc[2] = fmaf(v, f1.x, acc[2]); acc[3] = fmaf(v, f1.y, acc[3]);
        acc[4] = fmaf(v, f2.x, acc[4]); acc[5] = fmaf(v, f2.y, acc[5]);
        acc[6] = fmaf(v, f3.x, acc[6]); acc[7] = fmaf(v, f3.y, acc[7]);
    }

    // Combine the 4 edge-slots (xor over lane bits 3,4)
    #pragma unroll
    for (int j = 0; j < 8; j++) {
        acc[j] += __shfl_xor_sync(FULL, acc[j], 8);
        acc[j] += __shfl_xor_sync(FULL, acc[j], 16);
    }

    if (g == 0) {       // lanes 0..7: lane l owns cols l*8 .. l*8+7
        float4 b0 = __ldg((const float4*)bias + l * 2);
        float4 b1 = __ldg((const float4*)bias + l * 2 + 1);
        float4 o0, o1;
        o0.x = fmaxf(acc[0] + b0.x, 0.f);
        o0.y = fmaxf(acc[1] + b0.y, 0.f);
        o0.z = fmaxf(acc[2] + b0.z, 0.f);
        o0.w = fmaxf(acc[3] + b0.w, 0.f);
        o1.x = fmaxf(acc[4] + b1.x, 0.f);
        o1.y = fmaxf(acc[5] + b1.y, 0.f);
        o1.z = fmaxf(acc[6] + b1.z, 0.f);
        o1.w = fmaxf(acc[7] + b1.w, 0.f);
        float* dst = out + (size_t)row * ODIM + l * 8;
        *(float4*)(dst)     = o0;
        *(float4*)(dst + 4) = o1;
    }
}

// ---------------------------------------------------------------------------
extern "C" void kernel_launch(void* const* d_in, const int* in_sizes, int n_in,
                              void* d_out, int out_size) {
    const float* X     = (const float*)d_in[0];   // [N, 128]
    const int*   rows  = (const int*)  d_in[1];   // [E]
    const int*   cols  = (const int*)  d_in[2];   // [E]
    const float* vals  = (const float*)d_in[3];   // [E]
    const float* bases = (const float*)d_in[4];   // [4, 128, 64]
    const float* comp  = (const float*)d_in[5];   // [8, 4]
    const float* bias  = (const float*)d_in[6];   // [64]
    float* out = (float*)d_out;                   // [N, 64]

    int nN = in_sizes[0] / FDIM;
    int E  = in_sizes[1];

    cudaFuncSetAttribute(gemm_fw_kernel, cudaFuncAttributeMaxDynamicSharedMemorySize, SMEM_GEMM);

    // CSR build (independent of GEMM)
    zero_cnt_kernel<<<(nN + 255) / 256, 256>>>(nN);
    hist_kernel<<<(E + 255) / 256, 256>>>(rows, E);
    scan_kernel<<<1, 1024>>>(nN);
    scatter_kernel<<<(E + 255) / 256, 256>>>(rows, cols, vals, E);

    bcomb_kernel<<<(NBAS * FDIM * ODIM + 255) / 256, 256>>>(bases);

    int gblocks = (nN + 127) / 128;
    gemm_fw_kernel<<<gblocks, 512, SMEM_GEMM>>>(X, comp, nN);

    pull8_kernel<<<(nN + 7) / 8, 256>>>(out, bias, nN);
}